// round 2
// baseline (speedup 1.0000x reference)
#include <cuda_runtime.h>

// Problem constants (fixed by the dataset: x [256,2048,7,7], x0 [256,49,1])
#define BATCH   256
#define CDIM    2048
#define NDIM    49          // H*W = 7*7
#define TSZ     7           // tile size (7x7 tiles of the 49x49 Gram matrix)
#define CHUNK   32          // C rows per smem chunk
#define NSPLIT  8           // C-splits per tile
#define NTILES  28          // upper-triangular 7x7 tile pairs
#define THREADS 224         // 28 tiles * 8 splits = 7 warps
#define NCHUNK  (CDIM / CHUNK)          // 64
#define CHUNK_ELEMS (CHUNK * NDIM)      // 1568 == THREADS * 7
#define RSTRIDE 58          // smem row stride (floats): 7 groups of 8 + 2 pad, even, bank-friendly
#define EPSV    1e-12f

// tile index -> (group-ti, group-tj), ti <= tj, sorted by ti so warps share ti
__constant__ int c_ti[NTILES] = {0,0,0,0,0,0,0, 1,1,1,1,1,1, 2,2,2,2,2, 3,3,3,3, 4,4,4, 5,5, 6};
__constant__ int c_tj[NTILES] = {0,1,2,3,4,5,6, 1,2,3,4,5,6, 2,3,4,5,6, 3,4,5,6, 4,5,6, 5,6, 6};

// per-batch penalty scratch (no allocation allowed -> device global)
__device__ float g_penalty[BATCH];

typedef unsigned long long u64t;

__device__ __forceinline__ void fma2(u64t& d, u64t a, u64t b) {
    asm("fma.rn.f32x2 %0, %1, %2, %0;" : "+l"(d) : "l"(a), "l"(b));
}
__device__ __forceinline__ u64t bcast2(float v) {
    u64t r;
    asm("mov.b64 %0, {%1, %1};" : "=l"(r) : "r"(__float_as_uint(v)));
    return r;
}

// Block-wide sum over the first 49 lanes' values (all THREADS threads call this).
__device__ __forceinline__ float reduce49(float v, int t, float* sarr) {
    if (t < 64) sarr[t] = (t < NDIM) ? v : 0.0f;
    __syncthreads();
    if (t < 32) {
        float r = sarr[t] + sarr[t + 32];
        r += __shfl_xor_sync(0xffffffffu, r, 16);
        r += __shfl_xor_sync(0xffffffffu, r, 8);
        r += __shfl_xor_sync(0xffffffffu, r, 4);
        r += __shfl_xor_sync(0xffffffffu, r, 2);
        r += __shfl_xor_sync(0xffffffffu, r, 1);
        if (t == 0) sarr[0] = r;
    }
    __syncthreads();
    float out = sarr[0];
    __syncthreads();
    return out;
}

__global__ void __launch_bounds__(THREADS, 2)
ofpenalty_kernel(const float* __restrict__ x, const float* __restrict__ x0) {
    __shared__ float sbuf[2][CHUNK * RSTRIDE];   // group-expanded W chunks
    __shared__ float sA[NDIM * NDIM];            // Gram matrix
    __shared__ float sx[NDIM];                   // power-iteration vector
    __shared__ float sred[64];

    const int t     = threadIdx.x;
    const int b     = blockIdx.x;
    const int tile  = t >> 3;
    const int split = t & 7;
    const int ka = c_ti[tile];    // a group index (0..6)
    const int kb = c_tj[tile];    // b group index (0..6)
    const float* __restrict__ xb = x + (size_t)b * (CDIM * NDIM);

    // Precompute expanded smem store offsets for this thread's 7 chunk elements.
    int soff[7];
#pragma unroll
    for (int i = 0; i < 7; i++) {
        const int p = t + i * THREADS;      // linear index within a 1568-elem chunk
        const int r = p / NDIM;             // channel row within chunk (0..31)
        const int n = p % NDIM;             // col (0..48)
        soff[i] = r * RSTRIDE + 8 * (n / 7) + (n % 7);
    }

    // Zero the pad slots (8g+7) of both buffers: 32 rows * 7 groups = 224 = THREADS.
    {
        const int pr = t / 7, pg = t % 7;
        sbuf[0][pr * RSTRIDE + 8 * pg + 7] = 0.0f;
        sbuf[1][pr * RSTRIDE + 8 * pg + 7] = 0.0f;
    }

    // 7 rows x 4 pairs of packed fp32 accumulators (pair 3's hi lane hits the zero pad)
    u64t accp[TSZ][4];
#pragma unroll
    for (int i = 0; i < TSZ; i++)
#pragma unroll
        for (int j = 0; j < 4; j++) accp[i][j] = 0ull;

    // ---- load chunk 0 into expanded layout ----
#pragma unroll
    for (int i = 0; i < 7; i++) sbuf[0][soff[i]] = xb[t + i * THREADS];
    __syncthreads();

    // ---- streamed Gram accumulation (double-buffered) ----
    for (int ch = 0; ch < NCHUNK; ch++) {
        const int cur = ch & 1;

        // register prefetch of next chunk (1568 = 224*7, fully covered)
        float pre[7];
        if (ch + 1 < NCHUNK) {
            const float* __restrict__ src = xb + (size_t)(ch + 1) * CHUNK_ELEMS;
#pragma unroll
            for (int i = 0; i < 7; i++) pre[i] = __ldg(src + t + i * THREADS);
        }

#pragma unroll
        for (int cc = 0; cc < CHUNK / NSPLIT; cc++) {
            const float* __restrict__ row = &sbuf[cur][(cc * NSPLIT + split) * RSTRIDE];
            // b pairs: 4 aligned 8B loads from the expanded group (pad slot = 0)
            u64t bp[4];
#pragma unroll
            for (int j = 0; j < 4; j++)
                bp[j] = *reinterpret_cast<const u64t*>(row + 8 * kb + 2 * j);
#pragma unroll
            for (int i = 0; i < TSZ; i++) {
                const u64t ap = bcast2(row[8 * ka + i]);
#pragma unroll
                for (int j = 0; j < 4; j++) fma2(accp[i][j], ap, bp[j]);
            }
        }

        if (ch + 1 < NCHUNK) {
            const int nxt = cur ^ 1;
#pragma unroll
            for (int i = 0; i < 7; i++) sbuf[nxt][soff[i]] = pre[i];
        }
        __syncthreads();
    }

    // ---- reduce the 8 C-splits via 64-bit butterfly shuffles ----
#pragma unroll
    for (int i = 0; i < TSZ; i++)
#pragma unroll
        for (int j = 0; j < 4; j++) {
            u64t v = accp[i][j];
            // packed fp32 add of shuffled halves
            u64t s;
            s = __shfl_xor_sync(0xffffffffu, v, 4);
            asm("add.rn.f32x2 %0, %0, %1;" : "+l"(v) : "l"(s));
            s = __shfl_xor_sync(0xffffffffu, v, 2);
            asm("add.rn.f32x2 %0, %0, %1;" : "+l"(v) : "l"(s));
            s = __shfl_xor_sync(0xffffffffu, v, 1);
            asm("add.rn.f32x2 %0, %0, %1;" : "+l"(v) : "l"(s));
            accp[i][j] = v;
        }

    if (split == 0) {
        const int ti = ka * TSZ, tj = kb * TSZ;
#pragma unroll
        for (int i = 0; i < TSZ; i++)
#pragma unroll
            for (int j = 0; j < 4; j++) {
                const u64t v = accp[i][j];
                const float lo = __uint_as_float((unsigned)(v & 0xffffffffull));
                const float hi = __uint_as_float((unsigned)(v >> 32));
                const int cj = 2 * j;
                sA[(ti + i) * NDIM + (tj + cj)] = lo;
                sA[(tj + cj) * NDIM + (ti + i)] = lo;
                if (cj + 1 < TSZ) {
                    sA[(ti + i) * NDIM + (tj + cj + 1)] = hi;
                    sA[(tj + cj + 1) * NDIM + (ti + i)] = hi;
                }
            }
    }
    if (t < NDIM) sx[t] = x0[b * NDIM + t];
    __syncthreads();

    // ---- power iteration 1: largest eigenvalue of ATA ----
    for (int it = 0; it < 9; it++) {
        float y = 0.0f;
        if (t < NDIM) {
            float a0 = 0, a1 = 0, a2 = 0, a3 = 0;
            const float* __restrict__ rA = &sA[t * NDIM];
#pragma unroll
            for (int m = 0; m < 48; m += 4) {
                a0 = fmaf(rA[m + 0], sx[m + 0], a0);
                a1 = fmaf(rA[m + 1], sx[m + 1], a1);
                a2 = fmaf(rA[m + 2], sx[m + 2], a2);
                a3 = fmaf(rA[m + 3], sx[m + 3], a3);
            }
            y = (a0 + a1) + (a2 + a3) + rA[48] * sx[48];
        }
        const float n2  = reduce49(y * y, t, sred);
        const float nrm = fmaxf(sqrtf(n2), EPSV);
        if (t < NDIM) sx[t] = y / nrm;
        __syncthreads();
    }
    float y = 0.0f, xv = 0.0f;
    if (t < NDIM) {
        xv = sx[t];
        const float* __restrict__ rA = &sA[t * NDIM];
        float a0 = 0, a1 = 0, a2 = 0, a3 = 0;
#pragma unroll
        for (int m = 0; m < 48; m += 4) {
            a0 = fmaf(rA[m + 0], sx[m + 0], a0);
            a1 = fmaf(rA[m + 1], sx[m + 1], a1);
            a2 = fmaf(rA[m + 2], sx[m + 2], a2);
            a3 = fmaf(rA[m + 3], sx[m + 3], a3);
        }
        y = (a0 + a1) + (a2 + a3) + rA[48] * sx[48];
    }
    float num = reduce49(y * xv, t, sred);
    float den = reduce49(xv * xv, t, sred);
    const float largest = num / den;

    // ---- power iteration 2 on shifted matrix (ATA - largest*I), warm start x1 ----
    for (int it = 0; it < 9; it++) {
        float ys = 0.0f;
        if (t < NDIM) {
            float a0 = 0, a1 = 0, a2 = 0, a3 = 0;
            const float* __restrict__ rA = &sA[t * NDIM];
#pragma unroll
            for (int m = 0; m < 48; m += 4) {
                a0 = fmaf(rA[m + 0], sx[m + 0], a0);
                a1 = fmaf(rA[m + 1], sx[m + 1], a1);
                a2 = fmaf(rA[m + 2], sx[m + 2], a2);
                a3 = fmaf(rA[m + 3], sx[m + 3], a3);
            }
            ys = (a0 + a1) + (a2 + a3) + rA[48] * sx[48] - largest * sx[t];
        }
        const float n2  = reduce49(ys * ys, t, sred);
        const float nrm = fmaxf(sqrtf(n2), EPSV);
        if (t < NDIM) sx[t] = ys / nrm;
        __syncthreads();
    }
    y = 0.0f; xv = 0.0f;
    if (t < NDIM) {
        xv = sx[t];
        const float* __restrict__ rA = &sA[t * NDIM];
        float a0 = 0, a1 = 0, a2 = 0, a3 = 0;
#pragma unroll
        for (int m = 0; m < 48; m += 4) {
            a0 = fmaf(rA[m + 0], sx[m + 0], a0);
            a1 = fmaf(rA[m + 1], sx[m + 1], a1);
            a2 = fmaf(rA[m + 2], sx[m + 2], a2);
            a3 = fmaf(rA[m + 3], sx[m + 3], a3);
        }
        y = (a0 + a1) + (a2 + a3) + rA[48] * sx[48] - largest * xv;
    }
    num = reduce49(y * xv, t, sred);
    den = reduce49(xv * xv, t, sred);
    const float tmp      = num / den;
    const float smallest = tmp + largest;

    if (t == 0) {
        const float r = largest / smallest - 1.0f;
        g_penalty[b] = r * r;   // BETA = 1
    }
}

// Deterministic final reduction: sum(penalty)/B
__global__ void ofpenalty_finalize(float* __restrict__ out) {
    __shared__ float s[BATCH];
    const int t = threadIdx.x;
    s[t] = g_penalty[t];
    __syncthreads();
#pragma unroll
    for (int off = BATCH / 2; off > 0; off >>= 1) {
        if (t < off) s[t] += s[t + off];
        __syncthreads();
    }
    if (t == 0) out[0] = s[0] * (1.0f / (float)BATCH);
}

extern "C" void kernel_launch(void* const* d_in, const int* in_sizes, int n_in,
                              void* d_out, int out_size) {
    const float* x  = (const float*)d_in[0];   // [256, 2048, 7, 7]
    const float* x0 = (const float*)d_in[1];   // [256, 49, 1]
    float* out = (float*)d_out;

    ofpenalty_kernel<<<BATCH, THREADS>>>(x, x0);
    ofpenalty_finalize<<<1, BATCH>>>(out);
}

// round 4
// speedup vs baseline: 1.1024x; 1.1024x over previous
#include <cuda_runtime.h>
#include <cstdint>

// Problem constants (fixed: x [256,2048,7,7] fp32, x0 [256,49,1] fp32)
#define BATCH   256
#define CDIM    2048
#define NDIM    49
#define KCH     64                 // K (channels) per smem chunk
#define NCHUNKS 32                 // 2048/64
#define THREADS 256
#define SROW    72                 // floats per smem row: banks (8k+m)%32 -> conflict-free frags
#define BUF_FLOATS (KCH * SROW)    // 4608
#define EPSV    1e-12f

// dynamic smem layout (float indices)
#define OFF_BUF0  0
#define OFF_STAGE (3 * BUF_FLOATS)        // 13824 : 4 x 4096 reduction staging
#define OFF_SA    (OFF_STAGE + 4 * 4096)  // 30208 : 49x49 Gram
#define OFF_SX    (OFF_SA + 2432)
#define OFF_SRED  (OFF_SX + 64)
#define SMEM_FLOATS (OFF_SRED + 64)       // 32768 floats = 128 KB

__device__ float g_penalty[BATCH];

static __device__ __forceinline__ uint32_t f2tf32(float f) {
    uint32_t r;
    asm("cvt.rna.tf32.f32 %0, %1;" : "=r"(r) : "f"(f));
    return r;
}

// m16n8k4 tf32 mma (sm_80 PTX, valid on base sm_103):
// A frag: a0 (r=lane/4, k=lane%4), a1 (r=lane/4+8, k=lane%4)
// B frag: b0 (k=lane%4, c=lane/4)
// C frag: c0 (r=lane/4, c=2*(lane%4)), c1 (+1), c2 (r+8, c), c3 (r+8, c+1)
static __device__ __forceinline__ void mma_tf32(float* c, uint32_t a0, uint32_t a1, uint32_t b) {
    asm("mma.sync.aligned.m16n8k4.row.col.f32.tf32.tf32.f32 "
        "{%0,%1,%2,%3}, {%4,%5}, {%6}, {%0,%1,%2,%3};"
        : "+f"(c[0]), "+f"(c[1]), "+f"(c[2]), "+f"(c[3])
        : "r"(a0), "r"(a1), "r"(b));
}

// Block-wide sum over the first 49 lanes' values (all THREADS threads call this).
static __device__ __forceinline__ float reduce49(float v, int t, float* sarr) {
    if (t < 64) sarr[t] = (t < NDIM) ? v : 0.0f;
    __syncthreads();
    if (t < 32) {
        float r = sarr[t] + sarr[t + 32];
        r += __shfl_xor_sync(0xffffffffu, r, 16);
        r += __shfl_xor_sync(0xffffffffu, r, 8);
        r += __shfl_xor_sync(0xffffffffu, r, 4);
        r += __shfl_xor_sync(0xffffffffu, r, 2);
        r += __shfl_xor_sync(0xffffffffu, r, 1);
        if (t == 0) sarr[0] = r;
    }
    __syncthreads();
    float out = sarr[0];
    __syncthreads();
    return out;
}

extern __shared__ __align__(16) float smem[];

__global__ void __launch_bounds__(THREADS, 1)
ofp_mma_kernel(const float* __restrict__ x, const float* __restrict__ x0)
{
    const int t    = threadIdx.x;
    const int lane = t & 31;
    const int wid  = t >> 5;
    const int l4   = lane & 3;
    const int ld4  = lane >> 2;
    const int b    = blockIdx.x;

    float* sA   = &smem[OFF_SA];
    float* sx   = &smem[OFF_SX];
    float* sred = &smem[OFF_SRED];
    float* stg  = &smem[OFF_STAGE];

    const float* __restrict__ xb = x + (size_t)b * (CDIM * NDIM);

    // Zero-fill padded columns n in [49,64) of all 3 buffers once (never rewritten).
    for (int i = t; i < 3 * KCH * 15; i += THREADS) {
        const int bi = i / (KCH * 15);
        const int r  = (i - bi * KCH * 15) / 15;
        const int n  = 49 + (i - bi * KCH * 15) % 15;
        smem[bi * BUF_FLOATS + r * SROW + n] = 0.0f;
    }

    // Precompute this thread's 16 store offsets (chunk-invariant): flat -> (c,n) -> c*72+n
    int soff[16];
#pragma unroll
    for (int j = 0; j < 4; j++)
#pragma unroll
        for (int e = 0; e < 4; e++) {
            const int flat = (t + j * THREADS) * 4 + e;
            const int c    = flat / NDIM;
            const int n    = flat - c * NDIM;
            soff[j * 4 + e] = c * SROW + n;
        }

    // 64x64 fp32 accumulators: [mt 0..3][nt 0..7][ci 0..3]
    float acc[128];
#pragma unroll
    for (int i = 0; i < 128; i++) acc[i] = 0.0f;

    float4 rA[4];
    // ---- prologue: chunk0 -> buf0; chunk1 -> regs ----
    {
        const float4* __restrict__ s0 = (const float4*)xb;
#pragma unroll
        for (int j = 0; j < 4; j++)
            if (j < 3 || t < 16) rA[j] = __ldg(s0 + t + j * THREADS);
#pragma unroll
        for (int j = 0; j < 4; j++)
            if (j < 3 || t < 16) {
                smem[soff[j*4+0]] = __uint_as_float(f2tf32(rA[j].x));
                smem[soff[j*4+1]] = __uint_as_float(f2tf32(rA[j].y));
                smem[soff[j*4+2]] = __uint_as_float(f2tf32(rA[j].z));
                smem[soff[j*4+3]] = __uint_as_float(f2tf32(rA[j].w));
            }
        const float4* __restrict__ s1 = (const float4*)(xb + KCH * NDIM);
#pragma unroll
        for (int j = 0; j < 4; j++)
            if (j < 3 || t < 16) rA[j] = __ldg(s1 + t + j * THREADS);
    }
    __syncthreads();

    // ---- main loop: triple-buffered ----
    int bcur = 0;
    for (int ch = 0; ch < NCHUNKS; ch++) {
        const int bnxt = (bcur == 2) ? 0 : bcur + 1;
        // store chunk ch+1 (held in rA) into buf[bnxt]
        if (ch + 1 < NCHUNKS) {
            float* dst = &smem[bnxt * BUF_FLOATS];
#pragma unroll
            for (int j = 0; j < 4; j++)
                if (j < 3 || t < 16) {
                    dst[soff[j*4+0]] = __uint_as_float(f2tf32(rA[j].x));
                    dst[soff[j*4+1]] = __uint_as_float(f2tf32(rA[j].y));
                    dst[soff[j*4+2]] = __uint_as_float(f2tf32(rA[j].z));
                    dst[soff[j*4+3]] = __uint_as_float(f2tf32(rA[j].w));
                }
        }
        // prefetch chunk ch+2
        if (ch + 2 < NCHUNKS) {
            const float4* __restrict__ src = (const float4*)(xb + (size_t)(ch + 2) * (KCH * NDIM));
#pragma unroll
            for (int j = 0; j < 4; j++)
                if (j < 3 || t < 16) rA[j] = __ldg(src + t + j * THREADS);
        }
        // compute: this warp handles k = wid*8 .. wid*8+7 of the current chunk
        {
            const float* buf = &smem[bcur * BUF_FLOATS];
#pragma unroll
            for (int s = 0; s < 2; s++) {
                const float* rowp = buf + (wid * 8 + s * 4 + l4) * SROW;
                uint32_t bf[8];
#pragma unroll
                for (int nt = 0; nt < 8; nt++)
                    bf[nt] = __float_as_uint(rowp[nt * 8 + ld4]);
#pragma unroll
                for (int mt = 0; mt < 4; mt++) {
                    const uint32_t a0 = __float_as_uint(rowp[mt * 16 + ld4]);
                    const uint32_t a1 = __float_as_uint(rowp[mt * 16 + ld4 + 8]);
#pragma unroll
                    for (int nt = 0; nt < 8; nt++)
                        mma_tf32(&acc[(mt * 8 + nt) * 4], a0, a1, bf[nt]);
                }
            }
        }
        __syncthreads();
        bcur = bnxt;
    }

    // ---- k-split tree reduction across 8 warps (3 rounds, conflict-free staging) ----
    if (wid >= 4) {
        float* p = stg + (wid - 4) * 4096;
#pragma unroll
        for (int i = 0; i < 128; i++) p[i * 32 + lane] = acc[i];
    }
    __syncthreads();
    if (wid < 4) {
        const float* p = stg + wid * 4096;
#pragma unroll
        for (int i = 0; i < 128; i++) acc[i] += p[i * 32 + lane];
    }
    __syncthreads();
    if (wid == 2 || wid == 3) {
        float* p = stg + (wid - 2) * 4096;
#pragma unroll
        for (int i = 0; i < 128; i++) p[i * 32 + lane] = acc[i];
    }
    __syncthreads();
    if (wid < 2) {
        const float* p = stg + wid * 4096;
#pragma unroll
        for (int i = 0; i < 128; i++) acc[i] += p[i * 32 + lane];
    }
    __syncthreads();
    if (wid == 1) {
#pragma unroll
        for (int i = 0; i < 128; i++) stg[i * 32 + lane] = acc[i];
    }
    __syncthreads();
    if (wid == 0) {
#pragma unroll
        for (int i = 0; i < 128; i++) acc[i] += stg[i * 32 + lane];
        // write the 49x49 Gram: C frag (mt,nt,ci) -> (m,n)
#pragma unroll
        for (int mt = 0; mt < 4; mt++)
#pragma unroll
            for (int nt = 0; nt < 8; nt++)
#pragma unroll
                for (int ci = 0; ci < 4; ci++) {
                    const int m = mt * 16 + ld4 + ((ci >= 2) ? 8 : 0);
                    const int n = nt * 8 + 2 * l4 + (ci & 1);
                    if (m < NDIM && n < NDIM)
                        sA[m * NDIM + n] = acc[(mt * 8 + nt) * 4 + ci];
                }
    }
    if (t < NDIM) sx[t] = x0[b * NDIM + t];
    __syncthreads();

    // ---- power iteration 1: largest eigenvalue ----
    for (int it = 0; it < 9; it++) {
        float y = 0.0f;
        if (t < NDIM) {
            const float* __restrict__ rAo = &sA[t * NDIM];
#pragma unroll
            for (int m = 0; m < NDIM; m++) y = fmaf(rAo[m], sx[m], y);
        }
        const float n2  = reduce49(y * y, t, sred);
        const float nrm = fmaxf(sqrtf(n2), EPSV);
        if (t < NDIM) sx[t] = y / nrm;
        __syncthreads();
    }
    float y = 0.0f, xv = 0.0f;
    if (t < NDIM) {
        xv = sx[t];
        const float* __restrict__ rAo = &sA[t * NDIM];
#pragma unroll
        for (int m = 0; m < NDIM; m++) y = fmaf(rAo[m], sx[m], y);
    }
    float num = reduce49(y * xv, t, sred);
    float den = reduce49(xv * xv, t, sred);
    const float largest = num / den;

    // ---- power iteration 2 on (ATA - largest*I), warm start x1 ----
    for (int it = 0; it < 9; it++) {
        float ys = 0.0f;
        if (t < NDIM) {
            const float* __restrict__ rAo = &sA[t * NDIM];
#pragma unroll
            for (int m = 0; m < NDIM; m++) ys = fmaf(rAo[m], sx[m], ys);
            ys -= largest * sx[t];
        }
        const float n2  = reduce49(ys * ys, t, sred);
        const float nrm = fmaxf(sqrtf(n2), EPSV);
        if (t < NDIM) sx[t] = ys / nrm;
        __syncthreads();
    }
    y = 0.0f; xv = 0.0f;
    if (t < NDIM) {
        xv = sx[t];
        const float* __restrict__ rAo = &sA[t * NDIM];
#pragma unroll
        for (int m = 0; m < NDIM; m++) y = fmaf(rAo[m], sx[m], y);
        y -= largest * xv;
    }
    num = reduce49(y * xv, t, sred);
    den = reduce49(xv * xv, t, sred);
    const float smallest = (num / den) + largest;

    if (t == 0) {
        const float r = largest / smallest - 1.0f;
        g_penalty[b] = r * r;   // BETA = 1
    }
}

// Deterministic final reduction: sum(penalty)/B
__global__ void ofpenalty_finalize(float* __restrict__ out) {
    __shared__ float s[BATCH];
    const int t = threadIdx.x;
    s[t] = g_penalty[t];
    __syncthreads();
#pragma unroll
    for (int off = BATCH / 2; off > 0; off >>= 1) {
        if (t < off) s[t] += s[t + off];
        __syncthreads();
    }
    if (t == 0) out[0] = s[0] * (1.0f / (float)BATCH);
}

extern "C" void kernel_launch(void* const* d_in, const int* in_sizes, int n_in,
                              void* d_out, int out_size) {
    const float* x  = (const float*)d_in[0];   // [256, 2048, 7, 7]
    const float* x0 = (const float*)d_in[1];   // [256, 49, 1]
    float* out = (float*)d_out;

    static int configured = 0;
    if (!configured) {
        cudaFuncSetAttribute(ofp_mma_kernel,
                             cudaFuncAttributeMaxDynamicSharedMemorySize,
                             SMEM_FLOATS * sizeof(float));
        configured = 1;
    }
    ofp_mma_kernel<<<BATCH, THREADS, SMEM_FLOATS * sizeof(float)>>>(x, x0);
    ofpenalty_finalize<<<1, BATCH>>>(out);
}

// round 5
// speedup vs baseline: 1.4315x; 1.2985x over previous
#include <cuda_runtime.h>
#include <cstdint>

// Fixed problem: x [256,2048,7,7] fp32, x0 [256,49,1] fp32, out scalar fp32
#define BATCH   256
#define NQ      4                    // K-split partials per batch
#define NCTA    (BATCH * NQ)         // 1024
#define KQ      512                  // channels per CTA
#define KCH     64                   // channels per smem chunk
#define NCH     (KQ / KCH)           // 8
#define NDIM    49
#define SROW    72                   // floats/row: bank = (8k+n)%32 -> conflict-free frags
#define BUFF    (KCH * SROW)         // 4608 floats per buffer
#define THREADS 128
#define EPSV    1e-12f

__device__ float g_partial[NCTA][NDIM * NDIM];   // ~9.8 MB scratch
__device__ float g_penalty[BATCH];
__device__ int   g_cnt[BATCH];                   // zero-init; reset each run
__device__ int   g_cnt_all;

static __device__ __forceinline__ uint32_t f2tf32(float f) {
    uint32_t r;
    asm("cvt.rna.tf32.f32 %0, %1;" : "=r"(r) : "f"(f));
    return r;
}

// m16n8k8 tf32 (sm_80 PTX, valid on base sm_103). Standard fragment layouts.
static __device__ __forceinline__ void mma8(float* c,
    uint32_t a0, uint32_t a1, uint32_t a2, uint32_t a3,
    uint32_t b0, uint32_t b1)
{
    asm("mma.sync.aligned.m16n8k8.row.col.f32.tf32.tf32.f32 "
        "{%0,%1,%2,%3}, {%4,%5,%6,%7}, {%8,%9}, {%0,%1,%2,%3};"
        : "+f"(c[0]), "+f"(c[1]), "+f"(c[2]), "+f"(c[3])
        : "r"(a0), "r"(a1), "r"(a2), "r"(a3), "r"(b0), "r"(b1));
}

// Block-wide sum over first 49 lanes' values (all 128 threads call).
static __device__ __forceinline__ float reduce49(float v, int t, float* sarr) {
    if (t < 64) sarr[t] = (t < NDIM) ? v : 0.0f;
    __syncthreads();
    if (t < 32) {
        float r = sarr[t] + sarr[t + 32];
        r += __shfl_xor_sync(0xffffffffu, r, 16);
        r += __shfl_xor_sync(0xffffffffu, r, 8);
        r += __shfl_xor_sync(0xffffffffu, r, 4);
        r += __shfl_xor_sync(0xffffffffu, r, 2);
        r += __shfl_xor_sync(0xffffffffu, r, 1);
        if (t == 0) sarr[0] = r;
    }
    __syncthreads();
    float out = sarr[0];
    __syncthreads();
    return out;
}

// store a 64x49 chunk (held as 7 float4/thread) into [k][n] tf32 layout
static __device__ __forceinline__ void store_chunk(float* dst, const float4* pre, int t) {
#pragma unroll
    for (int i = 0; i < 7; i++) {
        if (i < 6 || t < 16) {
            const int flat = (t + i * THREADS) * 4;
            float v[4] = {pre[i].x, pre[i].y, pre[i].z, pre[i].w};
#pragma unroll
            for (int e = 0; e < 4; e++) {
                const int f = flat + e;
                const int c = f / NDIM;
                const int n = f - c * NDIM;
                dst[c * SROW + n] = __uint_as_float(f2tf32(v[e]));
            }
        }
    }
}

__global__ void __launch_bounds__(THREADS)
ofp_fused(const float* __restrict__ x, const float* __restrict__ x0,
          float* __restrict__ out)
{
    __shared__ float smem[2 * BUFF];          // 36864 B (static)
    float* sA    = smem;                      // [2401] aliases buf0 (dead by then)
    float* sx    = smem + 2432;
    float* sred  = smem + 2496;
    int*   scomm = (int*)(smem + 2560);
    float* sfin  = smem + BUFF;               // [128] final tree staging

    const int t    = threadIdx.x;
    const int lane = t & 31, wid = t >> 5;
    const int l4   = lane & 3, ld4 = lane >> 2;
    const int cta  = blockIdx.x;
    const int b    = cta >> 2, q = cta & 3;
    const int qm   = wid >> 1, qn = wid & 1;  // warp's 32x32 quadrant
    const int m0   = qm * 32 + ld4;
    const int n0   = qn * 32 + ld4;

    const float* __restrict__ xq =
        x + (size_t)b * (2048 * NDIM) + (size_t)q * (KQ * NDIM);

    // zero pad columns n in [49,64) of both buffers (read by frags, never refilled)
    for (int i = t; i < 2 * KCH * 15; i += THREADS) {
        const int bi = i / (KCH * 15);
        const int rem = i - bi * (KCH * 15);
        const int r = rem / 15;
        const int n = 49 + rem - r * 15;
        smem[bi * BUFF + r * SROW + n] = 0.0f;
    }

    float acc[2][4][4];
#pragma unroll
    for (int mt = 0; mt < 2; mt++)
#pragma unroll
        for (int nt = 0; nt < 4; nt++)
#pragma unroll
            for (int ci = 0; ci < 4; ci++) acc[mt][nt][ci] = 0.0f;

    // ---- prologue: chunk 0 -> buf0 ----
    float4 pre[7];
    {
        const float4* __restrict__ s0 = (const float4*)xq;
#pragma unroll
        for (int i = 0; i < 7; i++)
            if (i < 6 || t < 16) pre[i] = __ldg(s0 + t + i * THREADS);
        store_chunk(smem, pre, t);
    }
    __syncthreads();

    // ---- main loop: 8 chunks, double-buffered, 1 sync/iter ----
    for (int ch = 0; ch < NCH; ch++) {
        if (ch + 1 < NCH) {
            const float4* __restrict__ s1 =
                (const float4*)(xq + (size_t)(ch + 1) * (KCH * NDIM));
#pragma unroll
            for (int i = 0; i < 7; i++)
                if (i < 6 || t < 16) pre[i] = __ldg(s1 + t + i * THREADS);
        }
        const float* bc = smem + (ch & 1) * BUFF;
#pragma unroll
        for (int kb = 0; kb < 8; kb++) {
            const float* lo = bc + (kb * 8 + l4) * SROW;
            const float* hi = lo + 4 * SROW;
            uint32_t b0[4], b1[4];
#pragma unroll
            for (int nt = 0; nt < 4; nt++) {
                b0[nt] = __float_as_uint(lo[n0 + nt * 8]);
                b1[nt] = __float_as_uint(hi[n0 + nt * 8]);
            }
#pragma unroll
            for (int mt = 0; mt < 2; mt++) {
                const uint32_t a0 = __float_as_uint(lo[m0 + mt * 16]);
                const uint32_t a1 = __float_as_uint(lo[m0 + mt * 16 + 8]);
                const uint32_t a2 = __float_as_uint(hi[m0 + mt * 16]);
                const uint32_t a3 = __float_as_uint(hi[m0 + mt * 16 + 8]);
#pragma unroll
                for (int nt = 0; nt < 4; nt++)
                    mma8(acc[mt][nt], a0, a1, a2, a3, b0[nt], b1[nt]);
            }
        }
        if (ch + 1 < NCH) store_chunk(smem + ((ch + 1) & 1) * BUFF, pre, t);
        __syncthreads();
    }

    // ---- write 49x49 partial Gram ----
    {
        float* __restrict__ gp = g_partial[cta];
#pragma unroll
        for (int mt = 0; mt < 2; mt++)
#pragma unroll
            for (int nt = 0; nt < 4; nt++) {
                const int r0 = qm * 32 + mt * 16 + ld4;
                const int c0 = qn * 32 + nt * 8 + 2 * l4;
                const float* a = acc[mt][nt];
                if (r0 < NDIM) {
                    if (c0 < NDIM)     gp[r0 * NDIM + c0]     = a[0];
                    if (c0 + 1 < NDIM) gp[r0 * NDIM + c0 + 1] = a[1];
                }
                if (r0 + 8 < NDIM) {
                    if (c0 < NDIM)     gp[(r0 + 8) * NDIM + c0]     = a[2];
                    if (c0 + 1 < NDIM) gp[(r0 + 8) * NDIM + c0 + 1] = a[3];
                }
            }
    }
    __syncthreads();
    __threadfence();
    if (t == 0) scomm[0] = atomicAdd(&g_cnt[b], 1);
    __syncthreads();
    if (scomm[0] != NQ - 1) return;          // not the last partial of this batch

    // ================= last arriver: power iteration for batch b =================
    __threadfence();
    {
        const float* __restrict__ p0 = g_partial[(b << 2) + 0];
        const float* __restrict__ p1 = g_partial[(b << 2) + 1];
        const float* __restrict__ p2 = g_partial[(b << 2) + 2];
        const float* __restrict__ p3 = g_partial[(b << 2) + 3];
        for (int i = t; i < NDIM * NDIM; i += THREADS)
            sA[i] = (__ldcg(p0 + i) + __ldcg(p1 + i)) +
                    (__ldcg(p2 + i) + __ldcg(p3 + i));
    }
    if (t < NDIM) sx[t] = x0[b * NDIM + t];
    __syncthreads();

    // PI-1: largest eigenvalue of ATA
    for (int it = 0; it < 9; it++) {
        float y = 0.0f;
        if (t < NDIM) {
            const float* __restrict__ rA = &sA[t * NDIM];
#pragma unroll
            for (int m = 0; m < NDIM; m++) y = fmaf(rA[m], sx[m], y);
        }
        const float n2  = reduce49(y * y, t, sred);
        const float nrm = fmaxf(sqrtf(n2), EPSV);
        if (t < NDIM) sx[t] = y / nrm;
        __syncthreads();
    }
    float y = 0.0f, xv = 0.0f;
    if (t < NDIM) {
        xv = sx[t];
        const float* __restrict__ rA = &sA[t * NDIM];
#pragma unroll
        for (int m = 0; m < NDIM; m++) y = fmaf(rA[m], sx[m], y);
    }
    float num = reduce49(y * xv, t, sred);
    float den = reduce49(xv * xv, t, sred);
    const float largest = num / den;

    // PI-2 on (ATA - largest*I), warm-started from x1
    for (int it = 0; it < 9; it++) {
        float ys = 0.0f;
        if (t < NDIM) {
            const float* __restrict__ rA = &sA[t * NDIM];
#pragma unroll
            for (int m = 0; m < NDIM; m++) ys = fmaf(rA[m], sx[m], ys);
            ys -= largest * sx[t];
        }
        const float n2  = reduce49(ys * ys, t, sred);
        const float nrm = fmaxf(sqrtf(n2), EPSV);
        if (t < NDIM) sx[t] = ys / nrm;
        __syncthreads();
    }
    y = 0.0f; xv = 0.0f;
    if (t < NDIM) {
        xv = sx[t];
        const float* __restrict__ rA = &sA[t * NDIM];
#pragma unroll
        for (int m = 0; m < NDIM; m++) y = fmaf(rA[m], sx[m], y);
        y -= largest * xv;
    }
    num = reduce49(y * xv, t, sred);
    den = reduce49(xv * xv, t, sred);
    const float smallest = (num / den) + largest;

    if (t == 0) {
        const float r = largest / smallest - 1.0f;
        g_penalty[b] = r * r;                 // BETA = 1
    }
    __threadfence();
    if (t == 0) scomm[0] = atomicAdd(&g_cnt_all, 1);
    __syncthreads();
    if (scomm[0] != BATCH - 1) return;        // not the global last batch

    // ================= global last arriver: deterministic finalize =================
    __threadfence();
    sfin[t] = __ldcg(&g_penalty[t]) + __ldcg(&g_penalty[t + 128]);
    __syncthreads();
#pragma unroll
    for (int off = 64; off > 0; off >>= 1) {
        if (t < off) sfin[t] += sfin[t + off];
        __syncthreads();
    }
    if (t == 0) out[0] = sfin[0] * (1.0f / (float)BATCH);

    // reset counters for the next graph replay
    g_cnt[t] = 0;
    g_cnt[t + 128] = 0;
    if (t == 0) g_cnt_all = 0;
}

extern "C" void kernel_launch(void* const* d_in, const int* in_sizes, int n_in,
                              void* d_out, int out_size) {
    const float* x  = (const float*)d_in[0];   // [256, 2048, 7, 7]
    const float* x0 = (const float*)d_in[1];   // [256, 49, 1]
    float* out = (float*)d_out;

    ofp_fused<<<NCTA, THREADS>>>(x, x0, out);
}